// round 6
// baseline (speedup 1.0000x reference)
#include <cuda_runtime.h>

#define BATCH      16384
#define FIELD_DIM  100000

// scratch: per-row [s1(32) | s2(16)] block sums, 48 floats/row
__device__ float  g_scratch[BATCH * 48];
// pre-transposed weights: g_wT[k*32+l] = {W[2l][k], W[2l+1][k]} (k<32: W1, else W2)
__device__ float2 g_wT[48 * 32];
__device__ float2 g_bias[32];

// ---------------------------------------------------------------------------
// Kernel A: gather + segment-sum (blocks 0..2047, one row per warp).
// Block 2048 instead transposes W into g_wT (hidden under gather latency).
// ---------------------------------------------------------------------------
__global__ __launch_bounds__(256) void gather_kernel(
    const int*   __restrict__ x,    // [B, 26]
    const float* __restrict__ t0,   // [800000, 64]
    const float* __restrict__ t1,   // [800000, 32]
    const float* __restrict__ t2,   // [1000000, 16]
    const float* __restrict__ W1,   // [64, 32]
    const float* __restrict__ b1,   // [64]
    const float* __restrict__ W2,   // [64, 16]
    const float* __restrict__ b2,   // [64]
    float*       __restrict__ out)  // [B, 64]  (block0 sum, no bias)
{
    const int tid = threadIdx.x;

    if (blockIdx.x == BATCH / 8) {
        // ---- one-time W transpose + bias fold ----
        #pragma unroll
        for (int i = tid; i < 48 * 32; i += 256) {
            int k = i >> 5, l = i & 31;
            float a, b;
            if (k < 32) { a = W1[(2 * l) * 32 + k];        b = W1[(2 * l + 1) * 32 + k]; }
            else        { a = W2[(2 * l) * 16 + (k - 32)]; b = W2[(2 * l + 1) * 16 + (k - 32)]; }
            g_wT[i] = make_float2(a, b);
        }
        if (tid < 32)
            g_bias[tid] = make_float2(8.f * b1[2 * tid]     + 10.f * b2[2 * tid],
                                      8.f * b1[2 * tid + 1] + 10.f * b2[2 * tid + 1]);
        return;
    }

    const int warp = tid >> 5;
    const int lane = tid & 31;
    const unsigned FULL = 0xffffffffu;
    const int row = blockIdx.x * 8 + warp;

    int myidx = 0;
    if (lane < 26) myidx = x[row * 26 + lane];

    // ---- all gathers issued back-to-back (max MLP) ----
    float2 v0[8];
    #pragma unroll
    for (int f = 0; f < 8; f++) {
        int idx = __shfl_sync(FULL, myidx, f) + f * FIELD_DIM;
        v0[f] = ((const float2*)(t0 + (long long)idx * 64))[lane];     // 256B/warp
    }
    float v1[8];
    #pragma unroll
    for (int f = 0; f < 8; f++) {
        int idx = __shfl_sync(FULL, myidx, 8 + f) + f * FIELD_DIM;
        v1[f] = t1[(long long)idx * 32 + lane];                        // 128B/warp
    }
    const int half = lane >> 4;
    const int l16  = lane & 15;
    float v2[5];
    #pragma unroll
    for (int p = 0; p < 5; p++) {
        int f = 2 * p + half;
        int idx = __shfl_sync(FULL, myidx, 16 + f) + f * FIELD_DIM;
        v2[p] = t2[(long long)idx * 16 + l16];                         // 2 rows / 128B
    }

    // ---- reductions ----
    float2 acc = make_float2(0.f, 0.f);
    #pragma unroll
    for (int f = 0; f < 8; f++) { acc.x += v0[f].x; acc.y += v0[f].y; }

    float s1 = 0.f;
    #pragma unroll
    for (int f = 0; f < 8; f++) s1 += v1[f];

    float s2 = 0.f;
    #pragma unroll
    for (int p = 0; p < 5; p++) s2 += v2[p];
    s2 += __shfl_xor_sync(FULL, s2, 16);

    // ---- coalesced stores ----
    ((float2*)(out + (long long)row * 64))[lane] = acc;
    g_scratch[row * 48 + lane] = s1;
    if (lane < 16) g_scratch[row * 48 + 32 + lane] = s2;
}

// ---------------------------------------------------------------------------
// Kernel B: out += S[B,48] @ Wt[48,64] + bias.
// 16 rows/block, 2 rows/warp, grid 1024 -> ~7 blocks/SM, high occupancy.
// All independent global loads hoisted above the barrier.
// ---------------------------------------------------------------------------
__global__ __launch_bounds__(256) void proj_kernel(float* __restrict__ out)
{
    __shared__ float2 sW[48 * 32];      // 12 KB
    __shared__ float  sS[16 * 48];      // 3 KB

    const int tid  = threadIdx.x;
    const int warp = tid >> 5;
    const int lane = tid & 31;
    const int row0 = blockIdx.x * 16 + warp * 2;

    // ---- early independent loads (L2 hits, hidden under staging) ----
    const float2 bias = g_bias[lane];
    float2 p0 = ((const float2*)(out + (long long)(row0 + 0) * 64))[lane];
    float2 p1 = ((const float2*)(out + (long long)(row0 + 1) * 64))[lane];

    // stage W: 768 float4, 3 per thread (coalesced, L2-resident)
    {
        const float4* src = (const float4*)g_wT;
        float4* dst = (float4*)sW;
        #pragma unroll
        for (int i = tid; i < 768; i += 256) dst[i] = src[i];
    }
    // stage S: 16 rows x 48 floats = 192 float4
    {
        const float4* src = (const float4*)(g_scratch + (long long)blockIdx.x * 16 * 48);
        float4* dst = (float4*)sS;
        if (tid < 192) dst[tid] = src[tid];
    }
    __syncthreads();

    float2 acc0 = make_float2(p0.x + bias.x, p0.y + bias.y);
    float2 acc1 = make_float2(p1.x + bias.x, p1.y + bias.y);

    #pragma unroll
    for (int k4 = 0; k4 < 12; k4++) {
        float4 sa = *(const float4*)&sS[(warp * 2 + 0) * 48 + k4 * 4];  // uniform bcast
        float4 sb = *(const float4*)&sS[(warp * 2 + 1) * 48 + k4 * 4];

        #pragma unroll
        for (int j = 0; j < 4; j++) {
            float2 w = sW[(k4 * 4 + j) * 32 + lane];
            float va = (j == 0) ? sa.x : (j == 1) ? sa.y : (j == 2) ? sa.z : sa.w;
            float vb = (j == 0) ? sb.x : (j == 1) ? sb.y : (j == 2) ? sb.z : sb.w;
            acc0.x += w.x * va; acc0.y += w.y * va;
            acc1.x += w.x * vb; acc1.y += w.y * vb;
        }
    }

    ((float2*)(out + (long long)(row0 + 0) * 64))[lane] = acc0;
    ((float2*)(out + (long long)(row0 + 1) * 64))[lane] = acc1;
}

extern "C" void kernel_launch(void* const* d_in, const int* in_sizes, int n_in,
                              void* d_out, int out_size)
{
    const int*   x  = (const int*)  d_in[0];
    const float* t0 = (const float*)d_in[1];
    const float* t1 = (const float*)d_in[2];
    const float* t2 = (const float*)d_in[3];
    const float* W1 = (const float*)d_in[4];
    const float* b1 = (const float*)d_in[5];
    const float* W2 = (const float*)d_in[6];
    const float* b2 = (const float*)d_in[7];
    float* out = (float*)d_out;

    gather_kernel<<<BATCH / 8 + 1, 256>>>(x, t0, t1, t2, W1, b1, W2, b2, out);
    proj_kernel<<<BATCH / 16, 256>>>(out);
}

// round 7
// speedup vs baseline: 1.2909x; 1.2909x over previous
#include <cuda_runtime.h>

#define BATCH      16384
#define FIELD_DIM  100000
#define THREADS    256
#define WARPS      8
#define RPW        2
#define NBLOCKS    (BATCH / (WARPS * RPW))   // 1024
#define PAD        66                        // stride (floats) for transposed W rows

__global__ __launch_bounds__(THREADS) void fused_kernel(
    const int*   __restrict__ x,    // [B, 26]
    const float* __restrict__ t0,   // [800000, 64]
    const float* __restrict__ t1,   // [800000, 32]
    const float* __restrict__ t2,   // [1000000, 16]
    const float* __restrict__ W1,   // [64, 32]
    const float* __restrict__ b1,   // [64]
    const float* __restrict__ W2,   // [64, 16]
    const float* __restrict__ b2,   // [64]
    float*       __restrict__ out)  // [B, 64]
{
    // Transposed W with pad-66 rows: sW1f[k*PAD + o] = W1[o][k] (o=0..63, k=0..31)
    __shared__ float sW1f[32 * PAD];
    __shared__ float sW2f[16 * PAD];
    __shared__ float sBiasF[64];
    __shared__ float sS[WARPS][RPW][48];

    const int tid  = threadIdx.x;
    const int warp = tid >> 5;
    const int lane = tid & 31;
    const unsigned FULL = 0xffffffffu;

    // ---- stage W: coalesced LDG, transposed STS (2-way conflicts max) ----
    #pragma unroll
    for (int i = tid; i < 64 * 32; i += THREADS) {   // 8 per thread
        int o = i >> 5, k = i & 31;
        sW1f[k * PAD + o] = W1[i];
    }
    #pragma unroll
    for (int i = tid; i < 64 * 16; i += THREADS) {   // 4 per thread
        int o = i >> 4, k = i & 15;
        sW2f[k * PAD + o] = W2[i];
    }
    if (tid < 64) sBiasF[tid] = 8.f * b1[tid] + 10.f * b2[tid];
    __syncthreads();

    const int row0 = (blockIdx.x * WARPS + warp) * RPW;

    // ---- load indices for both rows ----
    int i0 = 0, i1 = 0;
    if (lane < 26) {
        i0 = x[(row0 + 0) * 26 + lane];
        i1 = x[(row0 + 1) * 26 + lane];
    }

    // ---- issue ALL gathers for both rows back-to-back (max MLP: 42/lane) ----
    float2 v0a[8], v0b[8];
    #pragma unroll
    for (int f = 0; f < 8; f++) {
        int ia = __shfl_sync(FULL, i0, f) + f * FIELD_DIM;
        int ib = __shfl_sync(FULL, i1, f) + f * FIELD_DIM;
        v0a[f] = ((const float2*)(t0 + (long long)ia * 64))[lane];
        v0b[f] = ((const float2*)(t0 + (long long)ib * 64))[lane];
    }
    float v1a[8], v1b[8];
    #pragma unroll
    for (int f = 0; f < 8; f++) {
        int ia = __shfl_sync(FULL, i0, 8 + f) + f * FIELD_DIM;
        int ib = __shfl_sync(FULL, i1, 8 + f) + f * FIELD_DIM;
        v1a[f] = t1[(long long)ia * 32 + lane];
        v1b[f] = t1[(long long)ib * 32 + lane];
    }
    const int half = lane >> 4;
    const int l16  = lane & 15;
    float v2a[5], v2b[5];
    #pragma unroll
    for (int p = 0; p < 5; p++) {
        int f = 2 * p + half;
        int ia = __shfl_sync(FULL, i0, 16 + f) + f * FIELD_DIM;
        int ib = __shfl_sync(FULL, i1, 16 + f) + f * FIELD_DIM;
        v2a[p] = t2[(long long)ia * 16 + l16];
        v2b[p] = t2[(long long)ib * 16 + l16];
    }

    // ---- reductions ----
    const float2 bias = *(const float2*)&sBiasF[2 * lane];
    float2 acc0 = bias, acc1 = bias;
    #pragma unroll
    for (int f = 0; f < 8; f++) {
        acc0.x += v0a[f].x; acc0.y += v0a[f].y;
        acc1.x += v0b[f].x; acc1.y += v0b[f].y;
    }

    float s1a = 0.f, s1b = 0.f;
    #pragma unroll
    for (int f = 0; f < 8; f++) { s1a += v1a[f]; s1b += v1b[f]; }

    float s2a = 0.f, s2b = 0.f;
    #pragma unroll
    for (int p = 0; p < 5; p++) { s2a += v2a[p]; s2b += v2b[p]; }
    s2a += __shfl_xor_sync(FULL, s2a, 16);
    s2b += __shfl_xor_sync(FULL, s2b, 16);

    // ---- stage block-sums for uniform broadcast ----
    sS[warp][0][lane] = s1a;
    sS[warp][1][lane] = s1b;
    if (lane < 16) {
        sS[warp][0][32 + lane] = s2a;
        sS[warp][1][32 + lane] = s2b;
    }
    __syncwarp();

    // ---- projection: 48 k-steps, W LDS amortized over 2 rows ----
    #pragma unroll
    for (int k4 = 0; k4 < 12; k4++) {
        float4 sa = *(const float4*)&sS[warp][0][k4 * 4];   // uniform bcast
        float4 sb = *(const float4*)&sS[warp][1][k4 * 4];
        #pragma unroll
        for (int j = 0; j < 4; j++) {
            const int k = k4 * 4 + j;                       // compile-time
            float2 w;
            if (k < 32) w = *(const float2*)&sW1f[k * PAD + 2 * lane];
            else        w = *(const float2*)&sW2f[(k - 32) * PAD + 2 * lane];
            float va = (j == 0) ? sa.x : (j == 1) ? sa.y : (j == 2) ? sa.z : sa.w;
            float vb = (j == 0) ? sb.x : (j == 1) ? sb.y : (j == 2) ? sb.z : sb.w;
            acc0.x += w.x * va; acc0.y += w.y * va;
            acc1.x += w.x * vb; acc1.y += w.y * vb;
        }
    }

    // ---- single coalesced store per row ----
    ((float2*)(out + (long long)(row0 + 0) * 64))[lane] = acc0;
    ((float2*)(out + (long long)(row0 + 1) * 64))[lane] = acc1;
}

extern "C" void kernel_launch(void* const* d_in, const int* in_sizes, int n_in,
                              void* d_out, int out_size)
{
    const int*   x  = (const int*)  d_in[0];
    const float* t0 = (const float*)d_in[1];
    const float* t1 = (const float*)d_in[2];
    const float* t2 = (const float*)d_in[3];
    const float* W1 = (const float*)d_in[4];
    const float* b1 = (const float*)d_in[5];
    const float* W2 = (const float*)d_in[6];
    const float* b2 = (const float*)d_in[7];
    float* out = (float*)d_out;

    fused_kernel<<<NBLOCKS, THREADS>>>(x, t0, t1, t2, W1, b1, W2, b2, out);
}